// round 14
// baseline (speedup 1.0000x reference)
#include <cuda_runtime.h>
#include <cuda_bf16.h>
#include <mma.h>
#include <math.h>
#include <stdint.h>

using namespace nvcuda;
typedef __nv_bfloat16 bf16;

// ---------------------------------------------------------------------------
// Problem constants: N=8192 rows, F=1024, H=2048, P=128
// ---------------------------------------------------------------------------
constexpr int Nrow = 8192;
constexpr int Fdim = 1024;
constexpr int Hdim = 2048;
constexpr int Pdim = 128;
constexpr float INV_T = 10.0f;   // 1 / TEMPERATURE

// ---------------------------------------------------------------------------
// Scratch (__device__ globals; no cudaMalloc allowed). Byte offsets.
// ---------------------------------------------------------------------------
constexpr size_t SZ_FEAT_BF  = (size_t)Nrow * Fdim * 2;
constexpr size_t SZ_H_BF     = (size_t)Nrow * Hdim * 2;
constexpr size_t SZ_W1_BF    = (size_t)Fdim * Hdim * 2;
constexpr size_t SZ_W2_BF    = (size_t)Hdim * Hdim * 2;
constexpr size_t SZ_W3_BF    = (size_t)Hdim * Pdim * 2;
constexpr size_t SZ_Z        = (size_t)Nrow * Pdim * 4;

constexpr size_t OFF_F1HI = 0;
constexpr size_t OFF_F1LO = OFF_F1HI + SZ_FEAT_BF;
constexpr size_t OFF_F2HI = OFF_F1LO + SZ_FEAT_BF;
constexpr size_t OFF_F2LO = OFF_F2HI + SZ_FEAT_BF;
constexpr size_t OFF_H1HI = OFF_F2LO + SZ_FEAT_BF;
constexpr size_t OFF_H1LO = OFF_H1HI + SZ_H_BF;
constexpr size_t OFF_H2HI = OFF_H1LO + SZ_H_BF;
constexpr size_t OFF_H2LO = OFF_H2HI + SZ_H_BF;
constexpr size_t OFF_W1HI = OFF_H2LO + SZ_H_BF;
constexpr size_t OFF_W1LO = OFF_W1HI + SZ_W1_BF;
constexpr size_t OFF_W2HI = OFF_W1LO + SZ_W1_BF;
constexpr size_t OFF_W2LO = OFF_W2HI + SZ_W2_BF;
constexpr size_t OFF_W3HI = OFF_W2LO + SZ_W2_BF;
constexpr size_t OFF_W3LO = OFF_W3HI + SZ_W3_BF;
constexpr size_t OFF_Z1   = OFF_W3LO + SZ_W3_BF;
constexpr size_t OFF_Z2   = OFF_Z1 + SZ_Z;
constexpr size_t OFF_POS  = OFF_Z2 + SZ_Z;
constexpr size_t OFF_LSE  = OFF_POS + Nrow * 4;
constexpr size_t SCRATCH_BYTES = OFF_LSE + Nrow * 4;

__device__ __align__(128) unsigned char g_scratch[SCRATCH_BYTES];

// ---------------------------------------------------------------------------
// Helpers: smem address + cp.async (sm_80 baseline ISA)
// ---------------------------------------------------------------------------
__device__ __forceinline__ uint32_t smem_u32(const void* p) {
    uint32_t a;
    asm("{ .reg .u64 t; cvta.to.shared.u64 t, %1; cvt.u32.u64 %0, t; }"
        : "=r"(a) : "l"(p));
    return a;
}
#define CP_ASYNC16(dst_u32, src_ptr)                                         \
    asm volatile("cp.async.cg.shared.global [%0], [%1], 16;"                 \
                 :: "r"(dst_u32), "l"(src_ptr) : "memory")
#define CP_COMMIT()  asm volatile("cp.async.commit_group;" ::: "memory")
#define CP_WAIT1()   asm volatile("cp.async.wait_group 1;" ::: "memory")
#define CP_WAIT0()   asm volatile("cp.async.wait_group 0;" ::: "memory")

// ---------------------------------------------------------------------------
// Prep: fp32 -> bf16 hi/lo split (elementwise)
// ---------------------------------------------------------------------------
__global__ void split_fp32(const float* __restrict__ x,
                           bf16* __restrict__ hi, bf16* __restrict__ lo, int n)
{
    int i = (blockIdx.x * blockDim.x + threadIdx.x) * 4;
    if (i >= n) return;
    float4 v = *(const float4*)(x + i);
    float vv[4] = {v.x, v.y, v.z, v.w};
#pragma unroll
    for (int j = 0; j < 4; j++) {
        bf16 h = __float2bfloat16(vv[j]);
        hi[i + j] = h;
        lo[i + j] = __float2bfloat16(vv[j] - __bfloat162float(h));
    }
}

// ---------------------------------------------------------------------------
// Prep: W[K,N] fp32 -> Wt_hi/Wt_lo [N,K] bf16 (tiled transpose + split)
// ---------------------------------------------------------------------------
__global__ void transpose_split(const float* __restrict__ W,
                                bf16* __restrict__ hi, bf16* __restrict__ lo,
                                int K, int N)
{
    __shared__ float t[32][33];
    int n0 = blockIdx.x * 32, k0 = blockIdx.y * 32;
    int tx = threadIdx.x, ty0 = threadIdx.y;  // block (32, 8)
#pragma unroll
    for (int p = 0; p < 4; p++) {
        int ty = ty0 + p * 8;
        t[ty][tx] = W[(size_t)(k0 + ty) * N + n0 + tx];
    }
    __syncthreads();
#pragma unroll
    for (int p = 0; p < 4; p++) {
        int ty = ty0 + p * 8;
        float v = t[tx][ty];                         // element (k0+tx, n0+ty)
        size_t o = (size_t)(n0 + ty) * K + k0 + tx;  // Wt[n][k]
        bf16 h = __float2bfloat16(v);
        hi[o] = h;
        lo[o] = __float2bfloat16(v - __bfloat162float(h));
    }
}

// ---------------------------------------------------------------------------
// WMMA bf16x3 GEMM, 64x64 warp tiles + cp.async double-buffered smem (BK=16):
//   C[m,n] = act( sum_k A[m,k]*Wt[n,k] + bias[n] )
// nvcuda::wmma + cp.async (both sm_80 baseline), static smem exactly 48 KB
// (2 stages x 4 tiles x 128 rows x 24 bf16; ldm=24, multiple of 8 elems).
// CTA 128x128, 4 warps (2m x 2n), warp tile 64x64 = 4x4 wmma frags.
// Pipeline: cp.async next stage -> commit -> wait_group(1) for current ->
// sync -> compute. No prefetch registers (R13's spill source removed);
// LDG latency overlaps compute via the async copy engine.
// Products per k16 step: hi*hi, lo*hi, hi*lo into one fp32 accumulator.
// ---------------------------------------------------------------------------
constexpr int ROWE = 24;   // padded row length in bf16 elements (48 B)

template <bool RELU, bool FP32OUT>
__global__ void __launch_bounds__(128)
gemm_wmma(const bf16* __restrict__ Ahi, const bf16* __restrict__ Alo,
          const bf16* __restrict__ Bhi, const bf16* __restrict__ Blo,
          const float* __restrict__ bias,
          float* __restrict__ Cf,
          bf16* __restrict__ Chi, bf16* __restrict__ Clo,
          int N, int K)
{
    // [stage][tile][row][col] ; tiles: 0=Ahi 1=Alo 2=Bhi 3=Blo ; 49152 B
    __shared__ __align__(16) bf16 sbuf[2][4][128][ROWE];

    const int tid  = threadIdx.x;
    const int wid  = tid >> 5;
    const int lane = tid & 31;
    const int wm   = wid & 1;        // warp m index (0..1) -> m offset wm*64
    const int wn   = wid >> 1;       // warp n index (0..1) -> n offset wn*64
    const int m0   = blockIdx.y * 128;
    const int n0   = blockIdx.x * 128;

    const bf16* gsrc[4] = { Ahi + (size_t)m0 * K, Alo + (size_t)m0 * K,
                            Bhi + (size_t)n0 * K, Blo + (size_t)n0 * K };
    const uint32_t sbase = smem_u32(&sbuf[0][0][0][0]);

    // Loader: 4 tiles x 128 rows x 2 chunks(16B) = 1024 chunks / 128 thr = 8.
    // c = tid + t*128 ; tile = c>>8 ; row = (c&255)>>1 ; ch = c&1.
#define ISSUE_STAGE(kb, stg)                                                  \
    do {                                                                      \
        const int kbase_ = (kb) * 16;                                         \
        _Pragma("unroll")                                                     \
        for (int t_ = 0; t_ < 8; t_++) {                                      \
            int c_ = tid + t_ * 128;                                          \
            int tile_ = c_ >> 8, ix_ = c_ & 255, row_ = ix_ >> 1, ch_ = ix_ & 1; \
            uint32_t dst_ = sbase                                             \
                + (uint32_t)((((stg) * 4 + tile_) * 128 + row_) * (ROWE * 2)  \
                             + ch_ * 16);                                     \
            CP_ASYNC16(dst_, gsrc[tile_] + (size_t)row_ * K + kbase_ + ch_ * 8); \
        }                                                                     \
        CP_COMMIT();                                                          \
    } while (0)

    wmma::fragment<wmma::accumulator, 16, 16, 16, float> acc[4][4];
#pragma unroll
    for (int mf = 0; mf < 4; mf++)
#pragma unroll
        for (int nf = 0; nf < 4; nf++) wmma::fill_fragment(acc[mf][nf], 0.f);

    const int nKb = K / 16;

    // ---- prologue: issue K-block 0 into stage 0 ----
    ISSUE_STAGE(0, 0);

    for (int kb = 0; kb < nKb; kb++) {
        const int cur = kb & 1;

        // issue next block into the other stage; copies overlap compute
        if (kb + 1 < nKb) { ISSUE_STAGE(kb + 1, (kb + 1) & 1); CP_WAIT1(); }
        else              { CP_WAIT0(); }
        __syncthreads();   // stage 'cur' complete + visible; prev reads done

        // ---- compute on stage 'cur' (one K16 step) ----
        wmma::fragment<wmma::matrix_a, 16, 16, 16, bf16, wmma::row_major> fah[4], fal[4];
#pragma unroll
        for (int mf = 0; mf < 4; mf++) {
            wmma::load_matrix_sync(fah[mf], &sbuf[cur][0][wm * 64 + mf * 16][0], ROWE);
            wmma::load_matrix_sync(fal[mf], &sbuf[cur][1][wm * 64 + mf * 16][0], ROWE);
        }
#pragma unroll
        for (int nf = 0; nf < 4; nf++) {
            // B^T is (k x n) col-major over sB[n][k] with ldm = ROWE
            wmma::fragment<wmma::matrix_b, 16, 16, 16, bf16, wmma::col_major> fbh, fbl;
            wmma::load_matrix_sync(fbh, &sbuf[cur][2][wn * 64 + nf * 16][0], ROWE);
            wmma::load_matrix_sync(fbl, &sbuf[cur][3][wn * 64 + nf * 16][0], ROWE);
#pragma unroll
            for (int mf = 0; mf < 4; mf++) {
                wmma::mma_sync(acc[mf][nf], fah[mf], fbh, acc[mf][nf]);  // hi*hi
                wmma::mma_sync(acc[mf][nf], fal[mf], fbh, acc[mf][nf]);  // lo*hi
                wmma::mma_sync(acc[mf][nf], fah[mf], fbl, acc[mf][nf]);  // hi*lo
            }
        }
        __syncthreads();   // reads of 'cur' done before it is refilled
    }
#undef ISSUE_STAGE

    // ---- epilogue: stage each 16x16 fragment through per-warp smem (1KB),
    // apply bias/activation with known (m, n), write out.
    float* staging = (float*)(&sbuf[0][0][0][0]) + wid * 256;   // 4 warps x 1KB
    const int r  = lane >> 1;            // 0..15 row within fragment
    const int c0 = (lane & 1) * 8;       // 0 or 8: 8 consecutive cols per lane

#pragma unroll
    for (int mf = 0; mf < 4; mf++) {
#pragma unroll
        for (int nf = 0; nf < 4; nf++) {
            wmma::store_matrix_sync(staging, acc[mf][nf], 16, wmma::mem_row_major);
            __syncwarp();
            const int m  = m0 + wm * 64 + mf * 16 + r;
            const int nb = n0 + wn * 64 + nf * 16 + c0;
            float4 b0 = *(const float4*)(bias + nb);
            float4 b1 = *(const float4*)(bias + nb + 4);
            float v[8];
#pragma unroll
            for (int j = 0; j < 8; j++) v[j] = staging[r * 16 + c0 + j];
            v[0] += b0.x; v[1] += b0.y; v[2] += b0.z; v[3] += b0.w;
            v[4] += b1.x; v[5] += b1.y; v[6] += b1.z; v[7] += b1.w;
            if (RELU) {
#pragma unroll
                for (int j = 0; j < 8; j++) v[j] = fmaxf(v[j], 0.f);
            }
            if (FP32OUT) {
                *(float4*)(Cf + (size_t)m * N + nb)     = make_float4(v[0], v[1], v[2], v[3]);
                *(float4*)(Cf + (size_t)m * N + nb + 4) = make_float4(v[4], v[5], v[6], v[7]);
            } else {
                size_t o = (size_t)m * N + nb;
#pragma unroll
                for (int j = 0; j < 8; j += 2) {
                    bf16 h0 = __float2bfloat16(v[j]);
                    bf16 h1 = __float2bfloat16(v[j + 1]);
                    bf16 l0 = __float2bfloat16(v[j]     - __bfloat162float(h0));
                    bf16 l1 = __float2bfloat16(v[j + 1] - __bfloat162float(h1));
                    *(__nv_bfloat162*)(Chi + o + j) = __nv_bfloat162(h0, h1);
                    *(__nv_bfloat162*)(Clo + o + j) = __nv_bfloat162(l0, l1);
                }
            }
            __syncwarp();   // staging reused by next fragment
        }
    }
}

// ---------------------------------------------------------------------------
// L2 normalize rows in place (P=128 -> one warp per row)
// ---------------------------------------------------------------------------
__global__ void norm_rows(float* __restrict__ Z)
{
    int row  = (blockIdx.x * blockDim.x + threadIdx.x) >> 5;
    int lane = threadIdx.x & 31;
    if (row >= Nrow) return;
    float4* p = (float4*)(Z + (size_t)row * Pdim) + lane;
    float4 v = *p;
    float ss = v.x * v.x + v.y * v.y + v.z * v.z + v.w * v.w;
#pragma unroll
    for (int o = 16; o > 0; o >>= 1) ss += __shfl_xor_sync(0xffffffffu, ss, o);
    float inv = 1.0f / fmaxf(sqrtf(ss), 1e-12f);
    v.x *= inv; v.y *= inv; v.z *= inv; v.w *= inv;
    *p = v;
}

// ---------------------------------------------------------------------------
// pos[i] = (1/T) * dot(r1_i, r2_i)
// ---------------------------------------------------------------------------
__global__ void pos_kernel(const float* __restrict__ R1,
                           const float* __restrict__ R2,
                           float* __restrict__ pos)
{
    int row  = (blockIdx.x * blockDim.x + threadIdx.x) >> 5;
    int lane = threadIdx.x & 31;
    if (row >= Nrow) return;
    float4 a = *((const float4*)(R1 + (size_t)row * Pdim) + lane);
    float4 b = *((const float4*)(R2 + (size_t)row * Pdim) + lane);
    float s = a.x * b.x + a.y * b.y + a.z * b.z + a.w * b.w;
#pragma unroll
    for (int o = 16; o > 0; o >>= 1) s += __shfl_xor_sync(0xffffffffu, s, o);
    if (lane == 0) pos[row] = INV_T * s;
}

// ---------------------------------------------------------------------------
// Fused logsumexp-GEMM (deterministic; never materializes 8192x8192)
// ---------------------------------------------------------------------------
constexpr int LI = 64, LJ = 64;

__global__ void __launch_bounds__(256, 1)
lse_kernel(const float* __restrict__ R1, const float* __restrict__ R2,
           float* __restrict__ lse)
{
    __shared__ float S1[Pdim][LI + 4];
    __shared__ float S2[32][LJ + 4];
    __shared__ float red[LI][17];

    const int tid = threadIdx.x;
    const int ti  = tid >> 4;
    const int tj  = tid & 15;
    const int i0  = blockIdx.x * LI;

#pragma unroll
    for (int p = 0; p < 8; p++) {
        int idx = tid + p * 256;
        int row = idx >> 5;
        int c4  = (idx & 31) << 2;
        float4 v = *(const float4*)(R1 + (size_t)(i0 + row) * Pdim + c4);
        S1[c4 + 0][row] = v.x; S1[c4 + 1][row] = v.y;
        S1[c4 + 2][row] = v.z; S1[c4 + 3][row] = v.w;
    }

    float sume[4] = {0.f, 0.f, 0.f, 0.f};

    for (int j0 = 0; j0 < Nrow; j0 += LJ) {
        float acc[4][4];
#pragma unroll
        for (int r = 0; r < 4; r++)
#pragma unroll
            for (int c = 0; c < 4; c++) acc[r][c] = 0.f;

#pragma unroll
        for (int kc = 0; kc < 4; kc++) {
            __syncthreads();
#pragma unroll
            for (int p = 0; p < 2; p++) {
                int idx = tid + p * 256;
                int row = idx >> 3;
                int c4  = (idx & 7) << 2;
                float4 v = *(const float4*)(R2 + (size_t)(j0 + row) * Pdim
                                            + kc * 32 + c4);
                S2[c4 + 0][row] = v.x; S2[c4 + 1][row] = v.y;
                S2[c4 + 2][row] = v.z; S2[c4 + 3][row] = v.w;
            }
            __syncthreads();
#pragma unroll
            for (int k = 0; k < 32; k++) {
                float4 a = *(const float4*)(&S1[kc * 32 + k][ti * 4]);
                float4 b = *(const float4*)(&S2[k][tj * 4]);
                float ra[4] = {a.x, a.y, a.z, a.w};
                float rb[4] = {b.x, b.y, b.z, b.w};
#pragma unroll
                for (int r = 0; r < 4; r++)
#pragma unroll
                    for (int c = 0; c < 4; c++)
                        acc[r][c] = fmaf(ra[r], rb[c], acc[r][c]);
            }
        }
#pragma unroll
        for (int r = 0; r < 4; r++) {
            sume[r] += __expf(INV_T * acc[r][0]) + __expf(INV_T * acc[r][1])
                     + __expf(INV_T * acc[r][2]) + __expf(INV_T * acc[r][3]);
        }
    }

    __syncthreads();
#pragma unroll
    for (int r = 0; r < 4; r++) red[ti * 4 + r][tj] = sume[r];
    __syncthreads();
    if (tid < LI) {
        float s = 0.f;
#pragma unroll
        for (int t = 0; t < 16; t++) s += red[tid][t];
        lse[i0 + tid] = logf(s);
    }
}

// ---------------------------------------------------------------------------
// Deterministic final reduction: out = mean(lse - pos)
// ---------------------------------------------------------------------------
__global__ void final_reduce(const float* __restrict__ lse,
                             const float* __restrict__ pos,
                             float* __restrict__ out)
{
    __shared__ float s[256];
    float acc = 0.f;
    for (int i = threadIdx.x; i < Nrow; i += 256) acc += lse[i] - pos[i];
    s[threadIdx.x] = acc;
    __syncthreads();
    for (int o = 128; o > 0; o >>= 1) {
        if (threadIdx.x < o) s[threadIdx.x] += s[threadIdx.x + o];
        __syncthreads();
    }
    if (threadIdx.x == 0) out[0] = s[0] / (float)Nrow;
}

// ---------------------------------------------------------------------------
// Launch (no cudaFuncSetAttribute needed: all static smem <= 48 KB)
// ---------------------------------------------------------------------------
extern "C" void kernel_launch(void* const* d_in, const int* in_sizes, int n_in,
                              void* d_out, int out_size)
{
    const float* f1 = (const float*)d_in[0];
    const float* f2 = (const float*)d_in[1];
    const float* W1 = (const float*)d_in[2];
    const float* b1 = (const float*)d_in[3];
    const float* W2 = (const float*)d_in[4];
    const float* b2 = (const float*)d_in[5];
    const float* W3 = (const float*)d_in[6];
    const float* b3 = (const float*)d_in[7];
    float* out = (float*)d_out;

    unsigned char* s = nullptr;
    cudaGetSymbolAddress((void**)&s, g_scratch);
    bf16* f1hi = (bf16*)(s + OFF_F1HI); bf16* f1lo = (bf16*)(s + OFF_F1LO);
    bf16* f2hi = (bf16*)(s + OFF_F2HI); bf16* f2lo = (bf16*)(s + OFF_F2LO);
    bf16* h1hi = (bf16*)(s + OFF_H1HI); bf16* h1lo = (bf16*)(s + OFF_H1LO);
    bf16* h2hi = (bf16*)(s + OFF_H2HI); bf16* h2lo = (bf16*)(s + OFF_H2LO);
    bf16* w1hi = (bf16*)(s + OFF_W1HI); bf16* w1lo = (bf16*)(s + OFF_W1LO);
    bf16* w2hi = (bf16*)(s + OFF_W2HI); bf16* w2lo = (bf16*)(s + OFF_W2LO);
    bf16* w3hi = (bf16*)(s + OFF_W3HI); bf16* w3lo = (bf16*)(s + OFF_W3LO);
    float* z1  = (float*)(s + OFF_Z1);  float* z2  = (float*)(s + OFF_Z2);
    float* pos = (float*)(s + OFF_POS); float* lse = (float*)(s + OFF_LSE);

    // ---- prep: weight transpose+split, feature split ----
    transpose_split<<<dim3(Hdim / 32, Fdim / 32), dim3(32, 8)>>>(W1, w1hi, w1lo, Fdim, Hdim);
    transpose_split<<<dim3(Hdim / 32, Hdim / 32), dim3(32, 8)>>>(W2, w2hi, w2lo, Hdim, Hdim);
    transpose_split<<<dim3(Pdim / 32, Hdim / 32), dim3(32, 8)>>>(W3, w3hi, w3lo, Hdim, Pdim);
    {
        int n = Nrow * Fdim;
        split_fp32<<<n / 4 / 256, 256>>>(f1, f1hi, f1lo, n);
        split_fp32<<<n / 4 / 256, 256>>>(f2, f2hi, f2lo, n);
    }

    const dim3 blk(128);
    const dim3 gHid(Hdim / 128, Nrow / 128);   // (16, 64)
    const dim3 gOut(Pdim / 128, Nrow / 128);   // ( 1, 64)

    // ---- branch 1 ----
    gemm_wmma<true , false><<<gHid, blk>>>(f1hi, f1lo, w1hi, w1lo, b1,
                                           nullptr, h1hi, h1lo, Hdim, Fdim);
    gemm_wmma<true , false><<<gHid, blk>>>(h1hi, h1lo, w2hi, w2lo, b2,
                                           nullptr, h2hi, h2lo, Hdim, Hdim);
    gemm_wmma<false, true ><<<gOut, blk>>>(h2hi, h2lo, w3hi, w3lo, b3,
                                           z1, nullptr, nullptr, Pdim, Hdim);
    norm_rows<<<Nrow / 8, 256>>>(z1);

    // ---- branch 2 (reuse h buffers) ----
    gemm_wmma<true , false><<<gHid, blk>>>(f2hi, f2lo, w1hi, w1lo, b1,
                                           nullptr, h1hi, h1lo, Hdim, Fdim);
    gemm_wmma<true , false><<<gHid, blk>>>(h1hi, h1lo, w2hi, w2lo, b2,
                                           nullptr, h2hi, h2lo, Hdim, Hdim);
    gemm_wmma<false, true ><<<gOut, blk>>>(h2hi, h2lo, w3hi, w3lo, b3,
                                           z2, nullptr, nullptr, Pdim, Hdim);
    norm_rows<<<Nrow / 8, 256>>>(z2);

    // ---- contrastive terms ----
    pos_kernel<<<Nrow / 8, 256>>>(z1, z2, pos);
    lse_kernel<<<Nrow / LI, 256>>>(z1, z2, lse);
    final_reduce<<<1, 256>>>(lse, pos, out);
}

// round 15
// speedup vs baseline: 1.3654x; 1.3654x over previous
#include <cuda_runtime.h>
#include <cuda_bf16.h>
#include <mma.h>
#include <math.h>
#include <stdint.h>

using namespace nvcuda;
typedef __nv_bfloat16 bf16;

// ---------------------------------------------------------------------------
// Problem constants: N=8192 rows, F=1024, H=2048, P=128
// ---------------------------------------------------------------------------
constexpr int Nrow = 8192;
constexpr int Fdim = 1024;
constexpr int Hdim = 2048;
constexpr int Pdim = 128;
constexpr float INV_T = 10.0f;   // 1 / TEMPERATURE

// ---------------------------------------------------------------------------
// Scratch (__device__ globals; no cudaMalloc allowed). Byte offsets.
// ---------------------------------------------------------------------------
constexpr size_t SZ_FEAT_BF  = (size_t)Nrow * Fdim * 2;
constexpr size_t SZ_H_BF     = (size_t)Nrow * Hdim * 2;
constexpr size_t SZ_W1_BF    = (size_t)Fdim * Hdim * 2;
constexpr size_t SZ_W2_BF    = (size_t)Hdim * Hdim * 2;
constexpr size_t SZ_W3_BF    = (size_t)Hdim * Pdim * 2;
constexpr size_t SZ_Z        = (size_t)Nrow * Pdim * 4;
constexpr size_t SZ_ZH       = (size_t)Nrow * Pdim * 2;
constexpr int    NSPLIT      = 4;

constexpr size_t OFF_F1HI = 0;
constexpr size_t OFF_F1LO = OFF_F1HI + SZ_FEAT_BF;
constexpr size_t OFF_F2HI = OFF_F1LO + SZ_FEAT_BF;
constexpr size_t OFF_F2LO = OFF_F2HI + SZ_FEAT_BF;
constexpr size_t OFF_H1HI = OFF_F2LO + SZ_FEAT_BF;
constexpr size_t OFF_H1LO = OFF_H1HI + SZ_H_BF;
constexpr size_t OFF_H2HI = OFF_H1LO + SZ_H_BF;
constexpr size_t OFF_H2LO = OFF_H2HI + SZ_H_BF;
constexpr size_t OFF_W1HI = OFF_H2LO + SZ_H_BF;
constexpr size_t OFF_W1LO = OFF_W1HI + SZ_W1_BF;
constexpr size_t OFF_W2HI = OFF_W1LO + SZ_W1_BF;
constexpr size_t OFF_W2LO = OFF_W2HI + SZ_W2_BF;
constexpr size_t OFF_W3HI = OFF_W2LO + SZ_W2_BF;
constexpr size_t OFF_W3LO = OFF_W3HI + SZ_W3_BF;
constexpr size_t OFF_Z1   = OFF_W3LO + SZ_W3_BF;
constexpr size_t OFF_Z2   = OFF_Z1 + SZ_Z;
constexpr size_t OFF_Z1H  = OFF_Z2 + SZ_Z;
constexpr size_t OFF_Z2H  = OFF_Z1H + SZ_ZH;
constexpr size_t OFF_PSUM = OFF_Z2H + SZ_ZH;
constexpr size_t OFF_POS  = OFF_PSUM + (size_t)NSPLIT * Nrow * 4;
constexpr size_t OFF_LSE  = OFF_POS + Nrow * 4;
constexpr size_t SCRATCH_BYTES = OFF_LSE + Nrow * 4;

__device__ __align__(128) unsigned char g_scratch[SCRATCH_BYTES];

// ---------------------------------------------------------------------------
// Prep: fp32 -> bf16 hi/lo split (elementwise)
// ---------------------------------------------------------------------------
__global__ void split_fp32(const float* __restrict__ x,
                           bf16* __restrict__ hi, bf16* __restrict__ lo, int n)
{
    int i = (blockIdx.x * blockDim.x + threadIdx.x) * 4;
    if (i >= n) return;
    float4 v = *(const float4*)(x + i);
    float vv[4] = {v.x, v.y, v.z, v.w};
#pragma unroll
    for (int j = 0; j < 4; j++) {
        bf16 h = __float2bfloat16(vv[j]);
        hi[i + j] = h;
        lo[i + j] = __float2bfloat16(vv[j] - __bfloat162float(h));
    }
}

// ---------------------------------------------------------------------------
// Prep: fp32 -> bf16 (hi only)
// ---------------------------------------------------------------------------
__global__ void to_bf16(const float* __restrict__ x, bf16* __restrict__ h, int n)
{
    int i = (blockIdx.x * blockDim.x + threadIdx.x) * 4;
    if (i >= n) return;
    float4 v = *(const float4*)(x + i);
    __nv_bfloat162 a(__float2bfloat16(v.x), __float2bfloat16(v.y));
    __nv_bfloat162 b(__float2bfloat16(v.z), __float2bfloat16(v.w));
    *(__nv_bfloat162*)(h + i)     = a;
    *(__nv_bfloat162*)(h + i + 2) = b;
}

// ---------------------------------------------------------------------------
// Prep: W[K,N] fp32 -> Wt_hi/Wt_lo [N,K] bf16 (tiled transpose + split)
// ---------------------------------------------------------------------------
__global__ void transpose_split(const float* __restrict__ W,
                                bf16* __restrict__ hi, bf16* __restrict__ lo,
                                int K, int N)
{
    __shared__ float t[32][33];
    int n0 = blockIdx.x * 32, k0 = blockIdx.y * 32;
    int tx = threadIdx.x, ty0 = threadIdx.y;  // block (32, 8)
#pragma unroll
    for (int p = 0; p < 4; p++) {
        int ty = ty0 + p * 8;
        t[ty][tx] = W[(size_t)(k0 + ty) * N + n0 + tx];
    }
    __syncthreads();
#pragma unroll
    for (int p = 0; p < 4; p++) {
        int ty = ty0 + p * 8;
        float v = t[tx][ty];                         // element (k0+tx, n0+ty)
        size_t o = (size_t)(n0 + ty) * K + k0 + tx;  // Wt[n][k]
        bf16 h = __float2bfloat16(v);
        hi[o] = h;
        lo[o] = __float2bfloat16(v - __bfloat162float(h));
    }
}

// ---------------------------------------------------------------------------
// WMMA bf16x3 GEMM, 64x64 warp tiles (exact R11 structure -- proven fastest):
//   C[m,n] = act( sum_k A[m,k]*Wt[n,k] + bias[n] )
// Pure nvcuda::wmma, static smem 40960 B, single-buffered BK=32.
// CTA 128x128, 4 warps (2m x 2n), warp tile 64x64 = 4x4 wmma frags.
// Products per k16 step: hi*hi, lo*hi, hi*lo into one fp32 accumulator.
// ---------------------------------------------------------------------------
constexpr int ROWE = 40;   // padded row length in bf16 elements (80 B)

template <bool RELU, bool FP32OUT>
__global__ void __launch_bounds__(128)
gemm_wmma(const bf16* __restrict__ Ahi, const bf16* __restrict__ Alo,
          const bf16* __restrict__ Bhi, const bf16* __restrict__ Blo,
          const float* __restrict__ bias,
          float* __restrict__ Cf,
          bf16* __restrict__ Chi, bf16* __restrict__ Clo,
          int N, int K)
{
    __shared__ __align__(16) bf16 sAhi[128][ROWE];
    __shared__ __align__(16) bf16 sAlo[128][ROWE];
    __shared__ __align__(16) bf16 sBhi[128][ROWE];
    __shared__ __align__(16) bf16 sBlo[128][ROWE];

    const int tid  = threadIdx.x;
    const int wid  = tid >> 5;
    const int lane = tid & 31;
    const int wm   = wid & 1;
    const int wn   = wid >> 1;
    const int m0   = blockIdx.y * 128;
    const int n0   = blockIdx.x * 128;

    const bf16* gsrc[4] = { Ahi + (size_t)m0 * K, Alo + (size_t)m0 * K,
                            Bhi + (size_t)n0 * K, Blo + (size_t)n0 * K };
    bf16* sdst[4] = { &sAhi[0][0], &sAlo[0][0], &sBhi[0][0], &sBlo[0][0] };

    wmma::fragment<wmma::accumulator, 16, 16, 16, float> acc[4][4];
#pragma unroll
    for (int mf = 0; mf < 4; mf++)
#pragma unroll
        for (int nf = 0; nf < 4; nf++) wmma::fill_fragment(acc[mf][nf], 0.f);

    const int nKb = K / 32;

    for (int kb = 0; kb < nKb; kb++) {
        const int kbase = kb * 32;
#pragma unroll
        for (int t = 0; t < 16; t++) {
            int c    = tid + t * 128;
            int tile = c >> 9;
            int ix   = c & 511;
            int row  = ix >> 2;
            int ch   = ix & 3;
            *(uint4*)(sdst[tile] + row * ROWE + ch * 8) =
                *(const uint4*)(gsrc[tile] + (size_t)row * K + kbase + ch * 8);
        }
        __syncthreads();

#pragma unroll
        for (int ks = 0; ks < 2; ks++) {
            wmma::fragment<wmma::matrix_a, 16, 16, 16, bf16, wmma::row_major> fah[4], fal[4];
#pragma unroll
            for (int mf = 0; mf < 4; mf++) {
                wmma::load_matrix_sync(fah[mf], &sAhi[wm * 64 + mf * 16][ks * 16], ROWE);
                wmma::load_matrix_sync(fal[mf], &sAlo[wm * 64 + mf * 16][ks * 16], ROWE);
            }
#pragma unroll
            for (int nf = 0; nf < 4; nf++) {
                wmma::fragment<wmma::matrix_b, 16, 16, 16, bf16, wmma::col_major> fbh, fbl;
                wmma::load_matrix_sync(fbh, &sBhi[wn * 64 + nf * 16][ks * 16], ROWE);
                wmma::load_matrix_sync(fbl, &sBlo[wn * 64 + nf * 16][ks * 16], ROWE);
#pragma unroll
                for (int mf = 0; mf < 4; mf++) {
                    wmma::mma_sync(acc[mf][nf], fah[mf], fbh, acc[mf][nf]);
                    wmma::mma_sync(acc[mf][nf], fal[mf], fbh, acc[mf][nf]);
                    wmma::mma_sync(acc[mf][nf], fah[mf], fbl, acc[mf][nf]);
                }
            }
        }
        __syncthreads();
    }

    float* staging = (float*)(&sAhi[0][0]) + wid * 256;
    const int r  = lane >> 1;
    const int c0 = (lane & 1) * 8;

#pragma unroll
    for (int mf = 0; mf < 4; mf++) {
#pragma unroll
        for (int nf = 0; nf < 4; nf++) {
            wmma::store_matrix_sync(staging, acc[mf][nf], 16, wmma::mem_row_major);
            __syncwarp();
            const int m  = m0 + wm * 64 + mf * 16 + r;
            const int nb = n0 + wn * 64 + nf * 16 + c0;
            float4 b0 = *(const float4*)(bias + nb);
            float4 b1 = *(const float4*)(bias + nb + 4);
            float v[8];
#pragma unroll
            for (int j = 0; j < 8; j++) v[j] = staging[r * 16 + c0 + j];
            v[0] += b0.x; v[1] += b0.y; v[2] += b0.z; v[3] += b0.w;
            v[4] += b1.x; v[5] += b1.y; v[6] += b1.z; v[7] += b1.w;
            if (RELU) {
#pragma unroll
                for (int j = 0; j < 8; j++) v[j] = fmaxf(v[j], 0.f);
            }
            if (FP32OUT) {
                *(float4*)(Cf + (size_t)m * N + nb)     = make_float4(v[0], v[1], v[2], v[3]);
                *(float4*)(Cf + (size_t)m * N + nb + 4) = make_float4(v[4], v[5], v[6], v[7]);
            } else {
                size_t o = (size_t)m * N + nb;
#pragma unroll
                for (int j = 0; j < 8; j += 2) {
                    bf16 h0 = __float2bfloat16(v[j]);
                    bf16 h1 = __float2bfloat16(v[j + 1]);
                    bf16 l0 = __float2bfloat16(v[j]     - __bfloat162float(h0));
                    bf16 l1 = __float2bfloat16(v[j + 1] - __bfloat162float(h1));
                    *(__nv_bfloat162*)(Chi + o + j) = __nv_bfloat162(h0, h1);
                    *(__nv_bfloat162*)(Clo + o + j) = __nv_bfloat162(l0, l1);
                }
            }
            __syncwarp();
        }
    }
}

// ---------------------------------------------------------------------------
// L2 normalize rows in place (P=128 -> one warp per row)
// ---------------------------------------------------------------------------
__global__ void norm_rows(float* __restrict__ Z)
{
    int row  = (blockIdx.x * blockDim.x + threadIdx.x) >> 5;
    int lane = threadIdx.x & 31;
    if (row >= Nrow) return;
    float4* p = (float4*)(Z + (size_t)row * Pdim) + lane;
    float4 v = *p;
    float ss = v.x * v.x + v.y * v.y + v.z * v.z + v.w * v.w;
#pragma unroll
    for (int o = 16; o > 0; o >>= 1) ss += __shfl_xor_sync(0xffffffffu, ss, o);
    float inv = 1.0f / fmaxf(sqrtf(ss), 1e-12f);
    v.x *= inv; v.y *= inv; v.z *= inv; v.w *= inv;
    *p = v;
}

// ---------------------------------------------------------------------------
// pos[i] = (1/T) * dot(r1_i, r2_i)  (fp32, exact)
// ---------------------------------------------------------------------------
__global__ void pos_kernel(const float* __restrict__ R1,
                           const float* __restrict__ R2,
                           float* __restrict__ pos)
{
    int row  = (blockIdx.x * blockDim.x + threadIdx.x) >> 5;
    int lane = threadIdx.x & 31;
    if (row >= Nrow) return;
    float4 a = *((const float4*)(R1 + (size_t)row * Pdim) + lane);
    float4 b = *((const float4*)(R2 + (size_t)row * Pdim) + lane);
    float s = a.x * b.x + a.y * b.y + a.z * b.z + a.w * b.w;
#pragma unroll
    for (int o = 16; o > 0; o >>= 1) s += __shfl_xor_sync(0xffffffffu, s, o);
    if (lane == 0) pos[row] = INV_T * s;
}

// ---------------------------------------------------------------------------
// Tensorized partial sum-of-exp:
//   psum[split][i] = sum_{j in split} exp( INV_T * r1_i . r2_j )
// bf16 single-product MMA (numerically safe here: errors average over 8192
// independent rows; final scalar error ~1e-5, threshold 1e-3).
// Block: 128 i-rows, 4 warps x 32 i-rows; A (r1) resident in fragments
// (2 mf x 8 k = 64 regs/warp, ZERO A reloads); B (r2) streamed through one
// 64-row smem tile. Grid (64 i-blocks, NSPLIT j-splits). Deterministic:
// fixed split bounds, fixed accumulation order, one writer per (i, split).
// ---------------------------------------------------------------------------
constexpr int KROWE = 136;             // 128 + 8 pad (ldm mult of 8)
constexpr int JT    = 64;              // j-tile
constexpr int JSPAN = Nrow / NSPLIT;   // 2048

__global__ void __launch_bounds__(128)
lse_mma(const bf16* __restrict__ R1h, const bf16* __restrict__ R2h,
        float* __restrict__ psum)
{
    __shared__ __align__(16) bf16 sB[JT][KROWE];     // 17408 B
    __shared__ __align__(16) float stag[4][256];     //  4096 B

    const int tid  = threadIdx.x;
    const int wid  = tid >> 5;
    const int lane = tid & 31;
    const int i0   = blockIdx.x * 128;
    const int split= blockIdx.y;
    const int j0b  = split * JSPAN;

    // ---- load resident A fragments (rows i0..i0+127) in two 64-row halves ----
    wmma::fragment<wmma::matrix_a, 16, 16, 16, bf16, wmma::row_major> fa[2][8];
#pragma unroll
    for (int half = 0; half < 2; half++) {
#pragma unroll
        for (int t = 0; t < 8; t++) {
            int c = tid + t * 128;
            int row = c >> 4, ch = c & 15;
            *(uint4*)(&sB[row][ch * 8]) =
                *(const uint4*)(R1h + (size_t)(i0 + half * 64 + row) * Pdim + ch * 8);
        }
        __syncthreads();
        if ((wid >> 1) == half) {          // warps 0,1 own rows 0..63; 2,3 own 64..127
            int rbase = (wid & 1) * 32;
#pragma unroll
            for (int mf = 0; mf < 2; mf++)
#pragma unroll
                for (int k = 0; k < 8; k++)
                    wmma::load_matrix_sync(fa[mf][k], &sB[rbase + mf * 16][k * 16], KROWE);
        }
        __syncthreads();
    }

    float sume[2] = {0.f, 0.f};
    const int r  = lane >> 1;
    const int c0 = (lane & 1) * 8;

    for (int jt = 0; jt < JSPAN / JT; jt++) {        // 32 iterations
        const int j0 = j0b + jt * JT;
        // load B tile: 64 rows x 16 chunks(16B) = 1024 / 128 thr = 8 each
#pragma unroll
        for (int t = 0; t < 8; t++) {
            int c = tid + t * 128;
            int row = c >> 4, ch = c & 15;
            *(uint4*)(&sB[row][ch * 8]) =
                *(const uint4*)(R2h + (size_t)(j0 + row) * Pdim + ch * 8);
        }
        __syncthreads();

        wmma::fragment<wmma::accumulator, 16, 16, 16, float> acc[2][4];
#pragma unroll
        for (int mf = 0; mf < 2; mf++)
#pragma unroll
            for (int nf = 0; nf < 4; nf++) wmma::fill_fragment(acc[mf][nf], 0.f);

#pragma unroll
        for (int nf = 0; nf < 4; nf++) {
#pragma unroll
            for (int k = 0; k < 8; k++) {
                wmma::fragment<wmma::matrix_b, 16, 16, 16, bf16, wmma::col_major> fb;
                wmma::load_matrix_sync(fb, &sB[nf * 16][k * 16], KROWE);
                wmma::mma_sync(acc[0][nf], fa[0][k], fb, acc[0][nf]);
                wmma::mma_sync(acc[1][nf], fa[1][k], fb, acc[1][nf]);
            }
        }

        // epilogue: exp + accumulate per-i partial sums (fixed order)
#pragma unroll
        for (int mf = 0; mf < 2; mf++) {
#pragma unroll
            for (int nf = 0; nf < 4; nf++) {
                wmma::store_matrix_sync(&stag[wid][0], acc[mf][nf], 16, wmma::mem_row_major);
                __syncwarp();
                float4 a = *(const float4*)(&stag[wid][r * 16 + c0]);
                float4 b = *(const float4*)(&stag[wid][r * 16 + c0 + 4]);
                sume[mf] += __expf(INV_T * a.x) + __expf(INV_T * a.y)
                          + __expf(INV_T * a.z) + __expf(INV_T * a.w)
                          + __expf(INV_T * b.x) + __expf(INV_T * b.y)
                          + __expf(INV_T * b.z) + __expf(INV_T * b.w);
                __syncwarp();
            }
        }
        __syncthreads();   // tile reads done before next refill
    }

    // combine the two lanes covering each row (lane 2r has c0=0, 2r+1 c0=8)
#pragma unroll
    for (int mf = 0; mf < 2; mf++) {
        float s = sume[mf];
        s += __shfl_xor_sync(0xffffffffu, s, 1);
        if ((lane & 1) == 0) {
            int i = i0 + wid * 32 + mf * 16 + r;
            psum[(size_t)split * Nrow + i] = s;
        }
    }
}

// ---------------------------------------------------------------------------
// lse[i] = log( sum over splits ), fixed order
// ---------------------------------------------------------------------------
__global__ void lse_combine(const float* __restrict__ psum, float* __restrict__ lse)
{
    int i = blockIdx.x * 256 + threadIdx.x;
    float s = psum[i];
#pragma unroll
    for (int p = 1; p < NSPLIT; p++) s += psum[(size_t)p * Nrow + i];
    lse[i] = logf(s);
}

// ---------------------------------------------------------------------------
// Deterministic final reduction: out = mean(lse - pos)
// ---------------------------------------------------------------------------
__global__ void final_reduce(const float* __restrict__ lse,
                             const float* __restrict__ pos,
                             float* __restrict__ out)
{
    __shared__ float s[256];
    float acc = 0.f;
    for (int i = threadIdx.x; i < Nrow; i += 256) acc += lse[i] - pos[i];
    s[threadIdx.x] = acc;
    __syncthreads();
    for (int o = 128; o > 0; o >>= 1) {
        if (threadIdx.x < o) s[threadIdx.x] += s[threadIdx.x + o];
        __syncthreads();
    }
    if (threadIdx.x == 0) out[0] = s[0] / (float)Nrow;
}

// ---------------------------------------------------------------------------
// Launch (no cudaFuncSetAttribute needed: all static smem <= 48 KB)
// ---------------------------------------------------------------------------
extern "C" void kernel_launch(void* const* d_in, const int* in_sizes, int n_in,
                              void* d_out, int out_size)
{
    const float* f1 = (const float*)d_in[0];
    const float* f2 = (const float*)d_in[1];
    const float* W1 = (const float*)d_in[2];
    const float* b1 = (const float*)d_in[3];
    const float* W2 = (const float*)d_in[4];
    const float* b2 = (const float*)d_in[5];
    const float* W3 = (const float*)d_in[6];
    const float* b3 = (const float*)d_in[7];
    float* out = (float*)d_out;

    unsigned char* s = nullptr;
    cudaGetSymbolAddress((void**)&s, g_scratch);
    bf16* f1hi = (bf16*)(s + OFF_F1HI); bf16* f1lo = (bf16*)(s + OFF_F1LO);
    bf16* f2hi = (bf16*)(s + OFF_F2HI); bf16* f2lo = (bf16*)(s + OFF_F2LO);
    bf16* h1hi = (bf16*)(s + OFF_H1HI); bf16* h1lo = (bf16*)(s + OFF_H1LO);
    bf16* h2hi = (bf16*)(s + OFF_H2HI); bf16* h2lo = (bf16*)(s + OFF_H2LO);
    bf16* w1hi = (bf16*)(s + OFF_W1HI); bf16* w1lo = (bf16*)(s + OFF_W1LO);
    bf16* w2hi = (bf16*)(s + OFF_W2HI); bf16* w2lo = (bf16*)(s + OFF_W2LO);
    bf16* w3hi = (bf16*)(s + OFF_W3HI); bf16* w3lo = (bf16*)(s + OFF_W3LO);
    float* z1  = (float*)(s + OFF_Z1);  float* z2  = (float*)(s + OFF_Z2);
    bf16* z1h  = (bf16*)(s + OFF_Z1H);  bf16* z2h  = (bf16*)(s + OFF_Z2H);
    float* psum= (float*)(s + OFF_PSUM);
    float* pos = (float*)(s + OFF_POS); float* lse = (float*)(s + OFF_LSE);

    // ---- prep: weight transpose+split, feature split ----
    transpose_split<<<dim3(Hdim / 32, Fdim / 32), dim3(32, 8)>>>(W1, w1hi, w1lo, Fdim, Hdim);
    transpose_split<<<dim3(Hdim / 32, Hdim / 32), dim3(32, 8)>>>(W2, w2hi, w2lo, Hdim, Hdim);
    transpose_split<<<dim3(Pdim / 32, Hdim / 32), dim3(32, 8)>>>(W3, w3hi, w3lo, Hdim, Pdim);
    {
        int n = Nrow * Fdim;
        split_fp32<<<n / 4 / 256, 256>>>(f1, f1hi, f1lo, n);
        split_fp32<<<n / 4 / 256, 256>>>(f2, f2hi, f2lo, n);
    }

    const dim3 blk(128);
    const dim3 gHid(Hdim / 128, Nrow / 128);   // (16, 64)
    const dim3 gOut(Pdim / 128, Nrow / 128);   // ( 1, 64)

    // ---- branch 1 ----
    gemm_wmma<true , false><<<gHid, blk>>>(f1hi, f1lo, w1hi, w1lo, b1,
                                           nullptr, h1hi, h1lo, Hdim, Fdim);
    gemm_wmma<true , false><<<gHid, blk>>>(h1hi, h1lo, w2hi, w2lo, b2,
                                           nullptr, h2hi, h2lo, Hdim, Hdim);
    gemm_wmma<false, true ><<<gOut, blk>>>(h2hi, h2lo, w3hi, w3lo, b3,
                                           z1, nullptr, nullptr, Pdim, Hdim);
    norm_rows<<<Nrow / 8, 256>>>(z1);

    // ---- branch 2 (reuse h buffers) ----
    gemm_wmma<true , false><<<gHid, blk>>>(f2hi, f2lo, w1hi, w1lo, b1,
                                           nullptr, h1hi, h1lo, Hdim, Fdim);
    gemm_wmma<true , false><<<gHid, blk>>>(h1hi, h1lo, w2hi, w2lo, b2,
                                           nullptr, h2hi, h2lo, Hdim, Hdim);
    gemm_wmma<false, true ><<<gOut, blk>>>(h2hi, h2lo, w3hi, w3lo, b3,
                                           z2, nullptr, nullptr, Pdim, Hdim);
    norm_rows<<<Nrow / 8, 256>>>(z2);

    // ---- contrastive terms ----
    {
        int n = Nrow * Pdim;
        to_bf16<<<n / 4 / 256, 256>>>(z1, z1h, n);
        to_bf16<<<n / 4 / 256, 256>>>(z2, z2h, n);
    }
    pos_kernel<<<Nrow / 8, 256>>>(z1, z2, pos);
    lse_mma<<<dim3(Nrow / 128, NSPLIT), 128>>>(z1h, z2h, psum);
    lse_combine<<<Nrow / 256, 256>>>(psum, lse);
    final_reduce<<<1, 256>>>(lse, pos, out);
}

// round 16
// speedup vs baseline: 1.5633x; 1.1450x over previous
#include <cuda_runtime.h>
#include <cuda_bf16.h>
#include <mma.h>
#include <math.h>
#include <stdint.h>

using namespace nvcuda;
typedef __nv_bfloat16 bf16;

// ---------------------------------------------------------------------------
// Problem constants: N=8192 rows, F=1024, H=2048, P=128
// Both branches run STACKED: M2 = 2N = 16384 rows through the MLP.
// ---------------------------------------------------------------------------
constexpr int Nrow = 8192;
constexpr int M2   = 2 * Nrow;       // stacked rows
constexpr int Fdim = 1024;
constexpr int Hdim = 2048;
constexpr int Pdim = 128;
constexpr float INV_T = 10.0f;       // 1 / TEMPERATURE

// ---------------------------------------------------------------------------
// Scratch (__device__ globals; no cudaMalloc allowed). Byte offsets.
// ---------------------------------------------------------------------------
constexpr size_t SZ_F_BF  = (size_t)M2 * Fdim * 2;    // stacked features (bf16)
constexpr size_t SZ_H_BF  = (size_t)M2 * Hdim * 2;    // stacked hidden  (bf16)
constexpr size_t SZ_W1_BF = (size_t)Fdim * Hdim * 2;
constexpr size_t SZ_W2_BF = (size_t)Hdim * Hdim * 2;
constexpr size_t SZ_W3_BF = (size_t)Hdim * Pdim * 2;
constexpr size_t SZ_Z     = (size_t)M2 * Pdim * 4;    // stacked z (fp32)
constexpr size_t SZ_ZH    = (size_t)M2 * Pdim * 2;    // stacked z (bf16)
constexpr int    NSPLIT   = 4;

constexpr size_t OFF_FHI  = 0;
constexpr size_t OFF_FLO  = OFF_FHI + SZ_F_BF;
constexpr size_t OFF_H1HI = OFF_FLO + SZ_F_BF;
constexpr size_t OFF_H1LO = OFF_H1HI + SZ_H_BF;
constexpr size_t OFF_H2HI = OFF_H1LO + SZ_H_BF;
constexpr size_t OFF_H2LO = OFF_H2HI + SZ_H_BF;
constexpr size_t OFF_W1HI = OFF_H2LO + SZ_H_BF;
constexpr size_t OFF_W1LO = OFF_W1HI + SZ_W1_BF;
constexpr size_t OFF_W2HI = OFF_W1LO + SZ_W1_BF;
constexpr size_t OFF_W2LO = OFF_W2HI + SZ_W2_BF;
constexpr size_t OFF_W3HI = OFF_W2LO + SZ_W2_BF;
constexpr size_t OFF_W3LO = OFF_W3HI + SZ_W3_BF;
constexpr size_t OFF_Z    = OFF_W3LO + SZ_W3_BF;      // z1 = rows [0,N), z2 = [N,2N)
constexpr size_t OFF_ZH   = OFF_Z + SZ_Z;
constexpr size_t OFF_PSUM = OFF_ZH + SZ_ZH;
constexpr size_t OFF_POS  = OFF_PSUM + (size_t)NSPLIT * Nrow * 4;
constexpr size_t OFF_LSE  = OFF_POS + Nrow * 4;
constexpr size_t SCRATCH_BYTES = OFF_LSE + Nrow * 4;

__device__ __align__(128) unsigned char g_scratch[SCRATCH_BYTES];

// ---------------------------------------------------------------------------
// Prep: fp32 -> bf16 hi/lo split (elementwise)
// ---------------------------------------------------------------------------
__global__ void split_fp32(const float* __restrict__ x,
                           bf16* __restrict__ hi, bf16* __restrict__ lo, int n)
{
    int i = (blockIdx.x * blockDim.x + threadIdx.x) * 4;
    if (i >= n) return;
    float4 v = *(const float4*)(x + i);
    float vv[4] = {v.x, v.y, v.z, v.w};
#pragma unroll
    for (int j = 0; j < 4; j++) {
        bf16 h = __float2bfloat16(vv[j]);
        hi[i + j] = h;
        lo[i + j] = __float2bfloat16(vv[j] - __bfloat162float(h));
    }
}

// ---------------------------------------------------------------------------
// Prep: W[K,N] fp32 -> Wt_hi/Wt_lo [N,K] bf16 (tiled transpose + split)
// ---------------------------------------------------------------------------
__global__ void transpose_split(const float* __restrict__ W,
                                bf16* __restrict__ hi, bf16* __restrict__ lo,
                                int K, int N)
{
    __shared__ float t[32][33];
    int n0 = blockIdx.x * 32, k0 = blockIdx.y * 32;
    int tx = threadIdx.x, ty0 = threadIdx.y;  // block (32, 8)
#pragma unroll
    for (int p = 0; p < 4; p++) {
        int ty = ty0 + p * 8;
        t[ty][tx] = W[(size_t)(k0 + ty) * N + n0 + tx];
    }
    __syncthreads();
#pragma unroll
    for (int p = 0; p < 4; p++) {
        int ty = ty0 + p * 8;
        float v = t[tx][ty];                         // element (k0+tx, n0+ty)
        size_t o = (size_t)(n0 + ty) * K + k0 + tx;  // Wt[n][k]
        bf16 h = __float2bfloat16(v);
        hi[o] = h;
        lo[o] = __float2bfloat16(v - __bfloat162float(h));
    }
}

// ---------------------------------------------------------------------------
// WMMA bf16x3 GEMM, 64x64 warp tiles (R11/R15 structure -- proven fastest):
//   C[m,n] = act( sum_k A[m,k]*Wt[n,k] + bias[n] )
// Pure nvcuda::wmma, static smem 40960 B, single-buffered BK=32.
// CTA 128x128, 4 warps (2m x 2n), warp tile 64x64 = 4x4 wmma frags.
// Products per k16 step: hi*hi, lo*hi, hi*lo into one fp32 accumulator.
// ---------------------------------------------------------------------------
constexpr int ROWE = 40;   // padded row length in bf16 elements (80 B)

template <bool RELU, bool FP32OUT>
__global__ void __launch_bounds__(128)
gemm_wmma(const bf16* __restrict__ Ahi, const bf16* __restrict__ Alo,
          const bf16* __restrict__ Bhi, const bf16* __restrict__ Blo,
          const float* __restrict__ bias,
          float* __restrict__ Cf,
          bf16* __restrict__ Chi, bf16* __restrict__ Clo,
          int N, int K)
{
    __shared__ __align__(16) bf16 sAhi[128][ROWE];
    __shared__ __align__(16) bf16 sAlo[128][ROWE];
    __shared__ __align__(16) bf16 sBhi[128][ROWE];
    __shared__ __align__(16) bf16 sBlo[128][ROWE];

    const int tid  = threadIdx.x;
    const int wid  = tid >> 5;
    const int lane = tid & 31;
    const int wm   = wid & 1;
    const int wn   = wid >> 1;
    const int m0   = blockIdx.y * 128;
    const int n0   = blockIdx.x * 128;

    const bf16* gsrc[4] = { Ahi + (size_t)m0 * K, Alo + (size_t)m0 * K,
                            Bhi + (size_t)n0 * K, Blo + (size_t)n0 * K };
    bf16* sdst[4] = { &sAhi[0][0], &sAlo[0][0], &sBhi[0][0], &sBlo[0][0] };

    wmma::fragment<wmma::accumulator, 16, 16, 16, float> acc[4][4];
#pragma unroll
    for (int mf = 0; mf < 4; mf++)
#pragma unroll
        for (int nf = 0; nf < 4; nf++) wmma::fill_fragment(acc[mf][nf], 0.f);

    const int nKb = K / 32;

    for (int kb = 0; kb < nKb; kb++) {
        const int kbase = kb * 32;
#pragma unroll
        for (int t = 0; t < 16; t++) {
            int c    = tid + t * 128;
            int tile = c >> 9;
            int ix   = c & 511;
            int row  = ix >> 2;
            int ch   = ix & 3;
            *(uint4*)(sdst[tile] + row * ROWE + ch * 8) =
                *(const uint4*)(gsrc[tile] + (size_t)row * K + kbase + ch * 8);
        }
        __syncthreads();

#pragma unroll
        for (int ks = 0; ks < 2; ks++) {
            wmma::fragment<wmma::matrix_a, 16, 16, 16, bf16, wmma::row_major> fah[4], fal[4];
#pragma unroll
            for (int mf = 0; mf < 4; mf++) {
                wmma::load_matrix_sync(fah[mf], &sAhi[wm * 64 + mf * 16][ks * 16], ROWE);
                wmma::load_matrix_sync(fal[mf], &sAlo[wm * 64 + mf * 16][ks * 16], ROWE);
            }
#pragma unroll
            for (int nf = 0; nf < 4; nf++) {
                wmma::fragment<wmma::matrix_b, 16, 16, 16, bf16, wmma::col_major> fbh, fbl;
                wmma::load_matrix_sync(fbh, &sBhi[wn * 64 + nf * 16][ks * 16], ROWE);
                wmma::load_matrix_sync(fbl, &sBlo[wn * 64 + nf * 16][ks * 16], ROWE);
#pragma unroll
                for (int mf = 0; mf < 4; mf++) {
                    wmma::mma_sync(acc[mf][nf], fah[mf], fbh, acc[mf][nf]);
                    wmma::mma_sync(acc[mf][nf], fal[mf], fbh, acc[mf][nf]);
                    wmma::mma_sync(acc[mf][nf], fah[mf], fbl, acc[mf][nf]);
                }
            }
        }
        __syncthreads();
    }

    float* staging = (float*)(&sAhi[0][0]) + wid * 256;
    const int r  = lane >> 1;
    const int c0 = (lane & 1) * 8;

#pragma unroll
    for (int mf = 0; mf < 4; mf++) {
#pragma unroll
        for (int nf = 0; nf < 4; nf++) {
            wmma::store_matrix_sync(staging, acc[mf][nf], 16, wmma::mem_row_major);
            __syncwarp();
            const int m  = m0 + wm * 64 + mf * 16 + r;
            const int nb = n0 + wn * 64 + nf * 16 + c0;
            float4 b0 = *(const float4*)(bias + nb);
            float4 b1 = *(const float4*)(bias + nb + 4);
            float v[8];
#pragma unroll
            for (int j = 0; j < 8; j++) v[j] = staging[r * 16 + c0 + j];
            v[0] += b0.x; v[1] += b0.y; v[2] += b0.z; v[3] += b0.w;
            v[4] += b1.x; v[5] += b1.y; v[6] += b1.z; v[7] += b1.w;
            if (RELU) {
#pragma unroll
                for (int j = 0; j < 8; j++) v[j] = fmaxf(v[j], 0.f);
            }
            if (FP32OUT) {
                *(float4*)(Cf + (size_t)m * N + nb)     = make_float4(v[0], v[1], v[2], v[3]);
                *(float4*)(Cf + (size_t)m * N + nb + 4) = make_float4(v[4], v[5], v[6], v[7]);
            } else {
                size_t o = (size_t)m * N + nb;
#pragma unroll
                for (int j = 0; j < 8; j += 2) {
                    bf16 h0 = __float2bfloat16(v[j]);
                    bf16 h1 = __float2bfloat16(v[j + 1]);
                    bf16 l0 = __float2bfloat16(v[j]     - __bfloat162float(h0));
                    bf16 l1 = __float2bfloat16(v[j + 1] - __bfloat162float(h1));
                    *(__nv_bfloat162*)(Chi + o + j) = __nv_bfloat162(h0, h1);
                    *(__nv_bfloat162*)(Clo + o + j) = __nv_bfloat162(l0, l1);
                }
            }
            __syncwarp();
        }
    }
}

// ---------------------------------------------------------------------------
// L2 normalize rows in place + emit bf16 copy (P=128 -> one warp per row)
// ---------------------------------------------------------------------------
__global__ void norm_rows_bf(float* __restrict__ Z, bf16* __restrict__ Zh, int nrows)
{
    int row  = (blockIdx.x * blockDim.x + threadIdx.x) >> 5;
    int lane = threadIdx.x & 31;
    if (row >= nrows) return;
    float4* p = (float4*)(Z + (size_t)row * Pdim) + lane;
    float4 v = *p;
    float ss = v.x * v.x + v.y * v.y + v.z * v.z + v.w * v.w;
#pragma unroll
    for (int o = 16; o > 0; o >>= 1) ss += __shfl_xor_sync(0xffffffffu, ss, o);
    float inv = 1.0f / fmaxf(sqrtf(ss), 1e-12f);
    v.x *= inv; v.y *= inv; v.z *= inv; v.w *= inv;
    *p = v;
    __nv_bfloat162 a(__float2bfloat16(v.x), __float2bfloat16(v.y));
    __nv_bfloat162 b(__float2bfloat16(v.z), __float2bfloat16(v.w));
    bf16* ph = Zh + (size_t)row * Pdim + lane * 4;
    *(__nv_bfloat162*)(ph)     = a;
    *(__nv_bfloat162*)(ph + 2) = b;
}

// ---------------------------------------------------------------------------
// pos[i] = (1/T) * dot(r1_i, r2_i)  (fp32, exact)
// ---------------------------------------------------------------------------
__global__ void pos_kernel(const float* __restrict__ R1,
                           const float* __restrict__ R2,
                           float* __restrict__ pos)
{
    int row  = (blockIdx.x * blockDim.x + threadIdx.x) >> 5;
    int lane = threadIdx.x & 31;
    if (row >= Nrow) return;
    float4 a = *((const float4*)(R1 + (size_t)row * Pdim) + lane);
    float4 b = *((const float4*)(R2 + (size_t)row * Pdim) + lane);
    float s = a.x * b.x + a.y * b.y + a.z * b.z + a.w * b.w;
#pragma unroll
    for (int o = 16; o > 0; o >>= 1) s += __shfl_xor_sync(0xffffffffu, s, o);
    if (lane == 0) pos[row] = INV_T * s;
}

// ---------------------------------------------------------------------------
// Tensorized partial sum-of-exp (R15 structure, proven):
//   psum[split][i] = sum_{j in split} exp( INV_T * r1_i . r2_j )
// A (r1) resident in fragments; B (r2) streamed through one 64-row tile.
// Deterministic: fixed split bounds, fixed accumulation order.
// ---------------------------------------------------------------------------
constexpr int KROWE = 136;             // 128 + 8 pad (ldm mult of 8)
constexpr int JT    = 64;              // j-tile
constexpr int JSPAN = Nrow / NSPLIT;   // 2048

__global__ void __launch_bounds__(128)
lse_mma(const bf16* __restrict__ R1h, const bf16* __restrict__ R2h,
        float* __restrict__ psum)
{
    __shared__ __align__(16) bf16 sB[JT][KROWE];     // 17408 B
    __shared__ __align__(16) float stag[4][256];     //  4096 B

    const int tid  = threadIdx.x;
    const int wid  = tid >> 5;
    const int lane = tid & 31;
    const int i0   = blockIdx.x * 128;
    const int split= blockIdx.y;
    const int j0b  = split * JSPAN;

    wmma::fragment<wmma::matrix_a, 16, 16, 16, bf16, wmma::row_major> fa[2][8];
#pragma unroll
    for (int half = 0; half < 2; half++) {
#pragma unroll
        for (int t = 0; t < 8; t++) {
            int c = tid + t * 128;
            int row = c >> 4, ch = c & 15;
            *(uint4*)(&sB[row][ch * 8]) =
                *(const uint4*)(R1h + (size_t)(i0 + half * 64 + row) * Pdim + ch * 8);
        }
        __syncthreads();
        if ((wid >> 1) == half) {
            int rbase = (wid & 1) * 32;
#pragma unroll
            for (int mf = 0; mf < 2; mf++)
#pragma unroll
                for (int k = 0; k < 8; k++)
                    wmma::load_matrix_sync(fa[mf][k], &sB[rbase + mf * 16][k * 16], KROWE);
        }
        __syncthreads();
    }

    float sume[2] = {0.f, 0.f};
    const int r  = lane >> 1;
    const int c0 = (lane & 1) * 8;

    for (int jt = 0; jt < JSPAN / JT; jt++) {
        const int j0 = j0b + jt * JT;
#pragma unroll
        for (int t = 0; t < 8; t++) {
            int c = tid + t * 128;
            int row = c >> 4, ch = c & 15;
            *(uint4*)(&sB[row][ch * 8]) =
                *(const uint4*)(R2h + (size_t)(j0 + row) * Pdim + ch * 8);
        }
        __syncthreads();

        wmma::fragment<wmma::accumulator, 16, 16, 16, float> acc[2][4];
#pragma unroll
        for (int mf = 0; mf < 2; mf++)
#pragma unroll
            for (int nf = 0; nf < 4; nf++) wmma::fill_fragment(acc[mf][nf], 0.f);

#pragma unroll
        for (int nf = 0; nf < 4; nf++) {
#pragma unroll
            for (int k = 0; k < 8; k++) {
                wmma::fragment<wmma::matrix_b, 16, 16, 16, bf16, wmma::col_major> fb;
                wmma::load_matrix_sync(fb, &sB[nf * 16][k * 16], KROWE);
                wmma::mma_sync(acc[0][nf], fa[0][k], fb, acc[0][nf]);
                wmma::mma_sync(acc[1][nf], fa[1][k], fb, acc[1][nf]);
            }
        }

#pragma unroll
        for (int mf = 0; mf < 2; mf++) {
#pragma unroll
            for (int nf = 0; nf < 4; nf++) {
                wmma::store_matrix_sync(&stag[wid][0], acc[mf][nf], 16, wmma::mem_row_major);
                __syncwarp();
                float4 a = *(const float4*)(&stag[wid][r * 16 + c0]);
                float4 b = *(const float4*)(&stag[wid][r * 16 + c0 + 4]);
                sume[mf] += __expf(INV_T * a.x) + __expf(INV_T * a.y)
                          + __expf(INV_T * a.z) + __expf(INV_T * a.w)
                          + __expf(INV_T * b.x) + __expf(INV_T * b.y)
                          + __expf(INV_T * b.z) + __expf(INV_T * b.w);
                __syncwarp();
            }
        }
        __syncthreads();
    }

#pragma unroll
    for (int mf = 0; mf < 2; mf++) {
        float s = sume[mf];
        s += __shfl_xor_sync(0xffffffffu, s, 1);
        if ((lane & 1) == 0) {
            int i = i0 + wid * 32 + mf * 16 + r;
            psum[(size_t)split * Nrow + i] = s;
        }
    }
}

// ---------------------------------------------------------------------------
// lse[i] = log( sum over splits ), fixed order
// ---------------------------------------------------------------------------
__global__ void lse_combine(const float* __restrict__ psum, float* __restrict__ lse)
{
    int i = blockIdx.x * 256 + threadIdx.x;
    float s = psum[i];
#pragma unroll
    for (int p = 1; p < NSPLIT; p++) s += psum[(size_t)p * Nrow + i];
    lse[i] = logf(s);
}

// ---------------------------------------------------------------------------
// Deterministic final reduction: out = mean(lse - pos)
// ---------------------------------------------------------------------------
__global__ void final_reduce(const float* __restrict__ lse,
                             const float* __restrict__ pos,
                             float* __restrict__ out)
{
    __shared__ float s[256];
    float acc = 0.f;
    for (int i = threadIdx.x; i < Nrow; i += 256) acc += lse[i] - pos[i];
    s[threadIdx.x] = acc;
    __syncthreads();
    for (int o = 128; o > 0; o >>= 1) {
        if (threadIdx.x < o) s[threadIdx.x] += s[threadIdx.x + o];
        __syncthreads();
    }
    if (threadIdx.x == 0) out[0] = s[0] / (float)Nrow;
}

// ---------------------------------------------------------------------------
// Launch: both branches stacked (M=16384) -> 3 GEMM launches instead of 6.
// ---------------------------------------------------------------------------
extern "C" void kernel_launch(void* const* d_in, const int* in_sizes, int n_in,
                              void* d_out, int out_size)
{
    const float* f1 = (const float*)d_in[0];
    const float* f2 = (const float*)d_in[1];
    const float* W1 = (const float*)d_in[2];
    const float* b1 = (const float*)d_in[3];
    const float* W2 = (const float*)d_in[4];
    const float* b2 = (const float*)d_in[5];
    const float* W3 = (const float*)d_in[6];
    const float* b3 = (const float*)d_in[7];
    float* out = (float*)d_out;

    unsigned char* s = nullptr;
    cudaGetSymbolAddress((void**)&s, g_scratch);
    bf16* fhi  = (bf16*)(s + OFF_FHI);  bf16* flo  = (bf16*)(s + OFF_FLO);
    bf16* h1hi = (bf16*)(s + OFF_H1HI); bf16* h1lo = (bf16*)(s + OFF_H1LO);
    bf16* h2hi = (bf16*)(s + OFF_H2HI); bf16* h2lo = (bf16*)(s + OFF_H2LO);
    bf16* w1hi = (bf16*)(s + OFF_W1HI); bf16* w1lo = (bf16*)(s + OFF_W1LO);
    bf16* w2hi = (bf16*)(s + OFF_W2HI); bf16* w2lo = (bf16*)(s + OFF_W2LO);
    bf16* w3hi = (bf16*)(s + OFF_W3HI); bf16* w3lo = (bf16*)(s + OFF_W3LO);
    float* z   = (float*)(s + OFF_Z);
    bf16*  zh  = (bf16*)(s + OFF_ZH);
    float* psum= (float*)(s + OFF_PSUM);
    float* pos = (float*)(s + OFF_POS); float* lse = (float*)(s + OFF_LSE);

    // ---- prep: weight transpose+split; features split into stacked buffer ----
    transpose_split<<<dim3(Hdim / 32, Fdim / 32), dim3(32, 8)>>>(W1, w1hi, w1lo, Fdim, Hdim);
    transpose_split<<<dim3(Hdim / 32, Hdim / 32), dim3(32, 8)>>>(W2, w2hi, w2lo, Hdim, Hdim);
    transpose_split<<<dim3(Pdim / 32, Hdim / 32), dim3(32, 8)>>>(W3, w3hi, w3lo, Hdim, Pdim);
    {
        int n = Nrow * Fdim;
        size_t off = (size_t)Nrow * Fdim;
        split_fp32<<<n / 4 / 256, 256>>>(f1, fhi, flo, n);
        split_fp32<<<n / 4 / 256, 256>>>(f2, fhi + off, flo + off, n);
    }

    const dim3 blk(128);
    const dim3 gHid(Hdim / 128, M2 / 128);   // (16, 128)
    const dim3 gOut(Pdim / 128, M2 / 128);   // ( 1, 128)

    // ---- stacked MLP: one chain over 16384 rows ----
    gemm_wmma<true , false><<<gHid, blk>>>(fhi, flo, w1hi, w1lo, b1,
                                           nullptr, h1hi, h1lo, Hdim, Fdim);
    gemm_wmma<true , false><<<gHid, blk>>>(h1hi, h1lo, w2hi, w2lo, b2,
                                           nullptr, h2hi, h2lo, Hdim, Hdim);
    gemm_wmma<false, true ><<<gOut, blk>>>(h2hi, h2lo, w3hi, w3lo, b3,
                                           z, nullptr, nullptr, Pdim, Hdim);
    norm_rows_bf<<<M2 / 8, 256>>>(z, zh, M2);

    // ---- contrastive terms (z1 = rows [0,N), z2 = rows [N,2N)) ----
    float* z1 = z;
    float* z2 = z + (size_t)Nrow * Pdim;
    bf16*  z1h = zh;
    bf16*  z2h = zh + (size_t)Nrow * Pdim;

    pos_kernel<<<Nrow / 8, 256>>>(z1, z2, pos);
    lse_mma<<<dim3(Nrow / 128, NSPLIT), 128>>>(z1h, z2h, psum);
    lse_combine<<<Nrow / 256, 256>>>(psum, lse);
    final_reduce<<<1, 256>>>(lse, pos, out);
}